// round 3
// baseline (speedup 1.0000x reference)
#include <cuda_runtime.h>
#include <math.h>

#define N_NODES 50000
#define N_EDGES 1600000
#define NH      72
#define NF1     146
#define NFH     152
#define BN_EPS  1e-5f
#define SF3     154

typedef unsigned long long u64;

// ---------------- device scratch ----------------
__device__ __align__(16) float g_zz[(size_t)N_EDGES * NH];   // edge pre-BN activations
__device__ __align__(16) float g_agg_h[N_NODES * NH];
__device__ __align__(16) float g_agg_x[N_NODES * 4];
__device__ float g_cnt[N_NODES];
__device__ __align__(16) float g_zh[N_NODES * NH];
__device__ float g_esum[NH], g_esq[NH], g_escale[NH], g_eshift[NH];
__device__ float g_hsum[NH], g_hsq[NH], g_hscale[NH], g_hshift[NH];

__device__ __forceinline__ float psi_f(float p) {
    return copysignf(log1pf(fabsf(p)), p);
}
__device__ __forceinline__ u64 pack2(float f) {
    u64 r; asm("mov.b64 %0, {%1, %1};" : "=l"(r) : "f"(f)); return r;
}
__device__ __forceinline__ void ffma2(u64& d, u64 a, u64 b) {
    asm("fma.rn.f32x2 %0, %1, %2, %0;" : "+l"(d) : "l"(a), "l"(b));
}
__device__ __forceinline__ float2 unpack2(u64 v) {
    float2 r; asm("mov.b64 {%0, %1}, %2;" : "=f"(r.x), "=f"(r.y) : "l"(v)); return r;
}

// inner product step: 36 channels (18 ffma2) against weight row in smem
__device__ __forceinline__ void fma_row(u64* acc, const float* wrow, float f) {
    u64 f2 = pack2(f);
    const ulonglong2* wr = (const ulonglong2*)wrow;
#pragma unroll
    for (int c2 = 0; c2 < 9; ++c2) {
        ulonglong2 w = wr[c2];
        ffma2(acc[2 * c2],     w.x, f2);
        ffma2(acc[2 * c2 + 1], w.y, f2);
    }
}

// ---------------- K0: zero accumulators ----------------
__global__ void k0_zero() {
    int idx = blockIdx.x * blockDim.x + threadIdx.x;
    int stride = gridDim.x * blockDim.x;
    for (int t = idx; t < N_NODES * NH; t += stride) g_agg_h[t] = 0.f;
    for (int t = idx; t < N_NODES * 4;  t += stride) g_agg_x[t] = 0.f;
    for (int t = idx; t < N_NODES;      t += stride) g_cnt[t]  = 0.f;
    if (idx < NH) { g_esum[idx] = 0.f; g_esq[idx] = 0.f; g_hsum[idx] = 0.f; g_hsq[idx] = 0.f; }
}

// ---------------- K1a: z = h_i @ We1[0:72] ----------------
__global__ __launch_bounds__(128) void k1a(const float* __restrict__ h,
                                           const int* __restrict__ ei,
                                           const float* __restrict__ We1) {
    __shared__ float sW[NH * NH];       // rows 0..71
    const int tid = threadIdx.x;
    for (int t = tid; t < NH * NH; t += 128) sW[t] = We1[t];
    __syncthreads();

    const int e = tid >> 1, c0 = (tid & 1) * 36;
    const int ge = blockIdx.x * 64 + e;
    const int i = ei[ge];
    const float4* hi = (const float4*)(h + (size_t)i * NH);

    u64 acc[18];
#pragma unroll
    for (int c = 0; c < 18; ++c) acc[c] = 0ull;

#pragma unroll 2
    for (int kc = 0; kc < 18; ++kc) {
        float4 f = hi[kc];
        fma_row(acc, sW + (kc * 4 + 0) * NH + c0, f.x);
        fma_row(acc, sW + (kc * 4 + 1) * NH + c0, f.y);
        fma_row(acc, sW + (kc * 4 + 2) * NH + c0, f.z);
        fma_row(acc, sW + (kc * 4 + 3) * NH + c0, f.w);
    }

    ulonglong2* zr = (ulonglong2*)(g_zz + (size_t)ge * NH + c0);
#pragma unroll
    for (int c2 = 0; c2 < 9; ++c2) {
        ulonglong2 o; o.x = acc[2 * c2]; o.y = acc[2 * c2 + 1];
        zr[c2] = o;
    }
}

// ---------------- K1b: z += [h_j, norms, dots] @ We1[72:146]; BN stats ----------------
__global__ __launch_bounds__(128) void k1b(const float* __restrict__ h,
                                           const float* __restrict__ x,
                                           const int* __restrict__ ei,
                                           const int* __restrict__ ej,
                                           const float* __restrict__ We1) {
    __shared__ float sW[74 * NH];       // rows 72..145
    const int tid = threadIdx.x;
    for (int t = tid; t < 74 * NH; t += 128) sW[t] = We1[NH * NH + t];
    __syncthreads();

    const int e = tid >> 1, c0 = (tid & 1) * 36;
    const int lane = tid & 31;
    const int ge = blockIdx.x * 64 + e;
    const int i = ei[ge], j = ej[ge];
    const float4* hj = (const float4*)(h + (size_t)j * NH);

    u64 acc[18];
    {
        const ulonglong2* zr = (const ulonglong2*)(g_zz + (size_t)ge * NH + c0);
#pragma unroll
        for (int c2 = 0; c2 < 9; ++c2) {
            ulonglong2 v = zr[c2];
            acc[2 * c2] = v.x; acc[2 * c2 + 1] = v.y;
        }
    }

#pragma unroll 2
    for (int kc = 0; kc < 18; ++kc) {
        float4 f = hj[kc];
        fma_row(acc, sW + (kc * 4 + 0) * NH + c0, f.x);
        fma_row(acc, sW + (kc * 4 + 1) * NH + c0, f.y);
        fma_row(acc, sW + (kc * 4 + 2) * NH + c0, f.z);
        fma_row(acc, sW + (kc * 4 + 3) * NH + c0, f.w);
    }
    {
        float4 xi = *(const float4*)(x + 4 * (size_t)i);
        float4 xj = *(const float4*)(x + 4 * (size_t)j);
        float dx0 = xi.x - xj.x, dx1 = xi.y - xj.y, dx2 = xi.z - xj.z, dx3 = xi.w - xj.w;
        float nsq = dx0 * dx0 - dx1 * dx1 - dx2 * dx2 - dx3 * dx3;
        float dsq = xi.x * xj.x - xi.y * xj.y - xi.z * xj.z - xi.w * xj.w;
        fma_row(acc, sW + 72 * NH + c0, psi_f(nsq));
        fma_row(acc, sW + 73 * NH + c0, psi_f(dsq));
    }

    // store z
    {
        ulonglong2* zr = (ulonglong2*)(g_zz + (size_t)ge * NH + c0);
#pragma unroll
        for (int c2 = 0; c2 < 9; ++c2) {
            ulonglong2 o; o.x = acc[2 * c2]; o.y = acc[2 * c2 + 1];
            zr[c2] = o;
        }
    }

    // BN stats (sum over 16 edges in warp)
    float a36[36];
#pragma unroll
    for (int c2 = 0; c2 < 18; ++c2) {
        float2 v = unpack2(acc[c2]);
        a36[2 * c2] = v.x; a36[2 * c2 + 1] = v.y;
    }
#pragma unroll
    for (int c = 0; c < 36; ++c) {
        float s = a36[c];
        float q = s * s;
#pragma unroll
        for (int msk = 2; msk <= 16; msk <<= 1) {
            s += __shfl_xor_sync(0xffffffffu, s, msk);
            q += __shfl_xor_sync(0xffffffffu, q, msk);
        }
        if ((lane >> 1) == 0) {
            atomicAdd(&g_esum[c0 + c], s);
            atomicAdd(&g_esq[c0 + c], q);
        }
    }
}

// ---------------- BN finalize ----------------
__global__ void kbn_finalize(const float* __restrict__ gamma, const float* __restrict__ beta,
                             float invM, int which) {
    int c = threadIdx.x;
    if (c >= NH) return;
    float s_, q_;
    if (which == 0) { s_ = g_esum[c]; q_ = g_esq[c]; }
    else            { s_ = g_hsum[c]; q_ = g_hsq[c]; }
    float mu  = s_ * invM;
    float var = q_ * invM - mu * mu;
    float sc  = gamma[c] * rsqrtf(var + BN_EPS);
    if (which == 0) { g_escale[c] = sc; g_eshift[c] = beta[c] - mu * sc; }
    else            { g_hscale[c] = sc; g_hshift[c] = beta[c] - mu * sc; }
}

// ---------------- K2a: a=relu(BN(z)); e=relu(a@We2+be2); w=sig(e@Wm+bm); m=e*w; agg ----------------
__global__ __launch_bounds__(128) void k2a(const int* __restrict__ ei,
                                           const float* __restrict__ We2, const float* __restrict__ be2,
                                           const float* __restrict__ Wm,  const float* __restrict__ bm,
                                           float* __restrict__ mout) {
    __shared__ float sW[NH * NH];
    __shared__ float sSc[NH], sSh[NH], sB[NH], sWm[NH];
    const int tid = threadIdx.x;
    for (int t = tid; t < NH * NH; t += 128) sW[t] = We2[t];
    if (tid < NH) { sSc[tid] = g_escale[tid]; sSh[tid] = g_eshift[tid]; sB[tid] = be2[tid]; sWm[tid] = Wm[tid]; }
    __syncthreads();

    const int e = tid >> 1, half = tid & 1, c0 = half * 36;
    const int ge = blockIdx.x * 64 + e;
    const int i = ei[ge];

    u64 acc[18];
#pragma unroll
    for (int c = 0; c < 18; ++c) acc[c] = 0ull;

    const float4* zr = (const float4*)(g_zz + (size_t)ge * NH);
#pragma unroll 2
    for (int kc = 0; kc < 18; ++kc) {
        float4 z = zr[kc];
        float4 sc = ((const float4*)sSc)[kc];
        float4 sh = ((const float4*)sSh)[kc];
        fma_row(acc, sW + (kc * 4 + 0) * NH + c0, fmaxf(z.x * sc.x + sh.x, 0.f));
        fma_row(acc, sW + (kc * 4 + 1) * NH + c0, fmaxf(z.y * sc.y + sh.y, 0.f));
        fma_row(acc, sW + (kc * 4 + 2) * NH + c0, fmaxf(z.z * sc.z + sh.z, 0.f));
        fma_row(acc, sW + (kc * 4 + 3) * NH + c0, fmaxf(z.w * sc.w + sh.w, 0.f));
    }

    float m36[36];
    float pd = 0.f;
#pragma unroll
    for (int c2 = 0; c2 < 18; ++c2) {
        float2 v = unpack2(acc[c2]);
        float v0 = fmaxf(v.x + sB[c0 + 2 * c2], 0.f);
        float v1 = fmaxf(v.y + sB[c0 + 2 * c2 + 1], 0.f);
        m36[2 * c2] = v0; m36[2 * c2 + 1] = v1;
        pd += v0 * sWm[c0 + 2 * c2] + v1 * sWm[c0 + 2 * c2 + 1];
    }
    pd += __shfl_xor_sync(0xffffffffu, pd, 1);
    float w = 1.f / (1.f + expf(-(pd + bm[0])));

    float* mr = mout + (size_t)ge * NH + c0;
    float* ar = g_agg_h + (size_t)i * NH + c0;
#pragma unroll
    for (int c4 = 0; c4 < 9; ++c4) {
        float4 mv = make_float4(m36[c4 * 4] * w, m36[c4 * 4 + 1] * w,
                                m36[c4 * 4 + 2] * w, m36[c4 * 4 + 3] * w);
        ((float4*)mr)[c4] = mv;
        atomicAdd((float4*)(ar + c4 * 4), mv);
    }
    if (half == 0) atomicAdd(&g_cnt[i], 1.f);
}

// ---------------- K2b: px = relu(m@Wx1+bx1)@Wx2; trans agg ----------------
__global__ __launch_bounds__(128) void k2b(const float* __restrict__ x,
                                           const int* __restrict__ ei, const int* __restrict__ ej,
                                           const float* __restrict__ Wx1, const float* __restrict__ bx1,
                                           const float* __restrict__ Wx2,
                                           const float* __restrict__ mout) {
    __shared__ float sW[NH * NH];
    __shared__ float sB[NH], sWx2[NH];
    const int tid = threadIdx.x;
    for (int t = tid; t < NH * NH; t += 128) sW[t] = Wx1[t];
    if (tid < NH) { sB[tid] = bx1[tid]; sWx2[tid] = Wx2[tid]; }
    __syncthreads();

    const int e = tid >> 1, half = tid & 1, c0 = half * 36;
    const int ge = blockIdx.x * 64 + e;

    u64 acc[18];
#pragma unroll
    for (int c = 0; c < 18; ++c) acc[c] = 0ull;

    const float4* mr = (const float4*)(mout + (size_t)ge * NH);
#pragma unroll 2
    for (int kc = 0; kc < 18; ++kc) {
        float4 f = mr[kc];
        fma_row(acc, sW + (kc * 4 + 0) * NH + c0, f.x);
        fma_row(acc, sW + (kc * 4 + 1) * NH + c0, f.y);
        fma_row(acc, sW + (kc * 4 + 2) * NH + c0, f.z);
        fma_row(acc, sW + (kc * 4 + 3) * NH + c0, f.w);
    }

    float px = 0.f;
#pragma unroll
    for (int c2 = 0; c2 < 18; ++c2) {
        float2 v = unpack2(acc[c2]);
        px += fmaxf(v.x + sB[c0 + 2 * c2], 0.f) * sWx2[c0 + 2 * c2];
        px += fmaxf(v.y + sB[c0 + 2 * c2 + 1], 0.f) * sWx2[c0 + 2 * c2 + 1];
    }
    px += __shfl_xor_sync(0xffffffffu, px, 1);

    if (half == 0) {
        const int i = ei[ge], j = ej[ge];
        float4 xi = *(const float4*)(x + 4 * (size_t)i);
        float4 xj = *(const float4*)(x + 4 * (size_t)j);
        float t0 = fminf(fmaxf((xi.x - xj.x) * px, -100.f), 100.f);
        float t1 = fminf(fmaxf((xi.y - xj.y) * px, -100.f), 100.f);
        float t2 = fminf(fmaxf((xi.z - xj.z) * px, -100.f), 100.f);
        float t3 = fminf(fmaxf((xi.w - xj.w) * px, -100.f), 100.f);
        atomicAdd((float4*)&g_agg_x[(size_t)i * 4], make_float4(t0, t1, t2, t3));
    }
}

// ---------------- K3a: node pass 1 ----------------
__global__ void k3a_node1(const float* __restrict__ h, const float* __restrict__ nattr,
                          const float* __restrict__ Wh1, const float* __restrict__ bh1) {
    extern __shared__ float sm[];
    float* sW = sm;
    float* sF = sW + NFH * NH;
    float* sB = sF + 64 * SF3;

    const int tid = threadIdx.x;
    for (int t = tid; t < NFH * NH; t += 128) sW[t] = Wh1[t];
    if (tid < NH) sB[tid] = bh1[tid];

    const int warp = tid >> 5, lane = tid & 31;
    const int nbase = blockIdx.x * 64;
    for (int t = 0; t < 16; ++t) {
        int ln = warp * 16 + t;
        int n = nbase + ln;
        float* f = sF + ln * SF3;
        if (n < N_NODES) {
            f[lane]       = h[(size_t)n * NH + lane];
            f[32 + lane]  = h[(size_t)n * NH + 32 + lane];
            f[72 + lane]  = g_agg_h[(size_t)n * NH + lane];
            f[104 + lane] = g_agg_h[(size_t)n * NH + 32 + lane];
            if (lane < 8) {
                f[64 + lane]  = h[(size_t)n * NH + 64 + lane];
                f[136 + lane] = g_agg_h[(size_t)n * NH + 64 + lane];
                f[144 + lane] = nattr[(size_t)n * 8 + lane];
            }
        } else {
            f[lane] = 0.f; f[32 + lane] = 0.f; f[72 + lane] = 0.f; f[104 + lane] = 0.f;
            if (lane < 8) { f[64 + lane] = 0.f; f[136 + lane] = 0.f; f[144 + lane] = 0.f; }
        }
    }
    __syncthreads();

    const int r = tid >> 1, c0 = (tid & 1) * 36;
    const int n = nbase + r;
    const bool valid = (n < N_NODES);

    u64 acc[18];
    {
        const u64* bp = (const u64*)(sB + c0);
#pragma unroll
        for (int c2 = 0; c2 < 18; ++c2) acc[c2] = bp[c2];
    }
    const float* fe = sF + r * SF3;
#pragma unroll 2
    for (int k = 0; k < NFH; ++k) fma_row(acc, sW + k * NH + c0, fe[k]);

    float a36[36];
#pragma unroll
    for (int c2 = 0; c2 < 18; ++c2) {
        float2 v = unpack2(acc[c2]);
        a36[2 * c2] = v.x; a36[2 * c2 + 1] = v.y;
    }
#pragma unroll
    for (int c = 0; c < 36; ++c) {
        float s = valid ? a36[c] : 0.f;
        float q = s * s;
#pragma unroll
        for (int msk = 2; msk <= 16; msk <<= 1) {
            s += __shfl_xor_sync(0xffffffffu, s, msk);
            q += __shfl_xor_sync(0xffffffffu, q, msk);
        }
        if ((lane >> 1) == 0) {
            atomicAdd(&g_hsum[c0 + c], s);
            atomicAdd(&g_hsq[c0 + c], q);
        }
    }

    if (valid) {
        ulonglong2* zr = (ulonglong2*)(g_zh + (size_t)n * NH + c0);
#pragma unroll
        for (int c2 = 0; c2 < 9; ++c2) {
            ulonglong2 o; o.x = acc[2 * c2]; o.y = acc[2 * c2 + 1];
            zr[c2] = o;
        }
    }
}

// ---------------- K3c: node pass 2 ----------------
__global__ __launch_bounds__(128) void k3c_node2(const float* __restrict__ h, const float* __restrict__ x,
                          const float* __restrict__ Wh2, const float* __restrict__ bh2,
                          float* __restrict__ hout, float* __restrict__ xout) {
    __shared__ float sW[NH * NH];
    __shared__ float sb[NH], sSc[NH], sSh[NH];
    const int tid = threadIdx.x;
    for (int t = tid; t < NH * NH; t += 128) sW[t] = Wh2[t];
    if (tid < NH) { sb[tid] = bh2[tid]; sSc[tid] = g_hscale[tid]; sSh[tid] = g_hshift[tid]; }
    __syncthreads();

    const int r = tid >> 1, half = tid & 1, c0 = half * 36;
    const int n = blockIdx.x * 64 + r;
    if (n >= N_NODES) return;

    u64 acc[18];
#pragma unroll
    for (int c = 0; c < 18; ++c) acc[c] = 0ull;

    const float4* zr = (const float4*)(g_zh + (size_t)n * NH);
#pragma unroll 2
    for (int kc = 0; kc < 18; ++kc) {
        float4 z = zr[kc];
        float4 sc = ((const float4*)sSc)[kc];
        float4 sh = ((const float4*)sSh)[kc];
        fma_row(acc, sW + (kc * 4 + 0) * NH + c0, fmaxf(z.x * sc.x + sh.x, 0.f));
        fma_row(acc, sW + (kc * 4 + 1) * NH + c0, fmaxf(z.y * sc.y + sh.y, 0.f));
        fma_row(acc, sW + (kc * 4 + 2) * NH + c0, fmaxf(z.z * sc.z + sh.z, 0.f));
        fma_row(acc, sW + (kc * 4 + 3) * NH + c0, fmaxf(z.w * sc.w + sh.w, 0.f));
    }

    const float* hr = h + (size_t)n * NH + c0;
    float* orow = hout + (size_t)n * NH + c0;
#pragma unroll
    for (int c4 = 0; c4 < 9; ++c4) {
        float2 v0 = unpack2(acc[2 * c4]);
        float2 v1 = unpack2(acc[2 * c4 + 1]);
        float4 hv = ((const float4*)hr)[c4];
        int c = c0 + c4 * 4;
        ((float4*)orow)[c4] = make_float4(hv.x + v0.x + sb[c + 0],
                                          hv.y + v0.y + sb[c + 1],
                                          hv.z + v1.x + sb[c + 2],
                                          hv.w + v1.y + sb[c + 3]);
    }
    if (half == 0) {
        float4 xi = *(const float4*)(x + 4 * (size_t)n);
        float4 ax = *(const float4*)(g_agg_x + 4 * (size_t)n);
        float inv = 1.f / fmaxf(g_cnt[n], 1.f);
        *(float4*)(xout + 4 * (size_t)n) =
            make_float4(xi.x + ax.x * inv, xi.y + ax.y * inv,
                        xi.z + ax.z * inv, xi.w + ax.w * inv);
    }
}

// ---------------- launch ----------------
extern "C" void kernel_launch(void* const* d_in, const int* in_sizes, int n_in,
                              void* d_out, int out_size) {
    const float* h      = (const float*)d_in[0];
    const float* x      = (const float*)d_in[1];
    const float* nattr  = (const float*)d_in[2];
    const int*   edges  = (const int*)d_in[3];
    const float* We1    = (const float*)d_in[4];
    const float* bn_e_g = (const float*)d_in[5];
    const float* bn_e_b = (const float*)d_in[6];
    const float* We2    = (const float*)d_in[7];
    const float* be2    = (const float*)d_in[8];
    const float* Wh1    = (const float*)d_in[9];
    const float* bh1    = (const float*)d_in[10];
    const float* bn_h_g = (const float*)d_in[11];
    const float* bn_h_b = (const float*)d_in[12];
    const float* Wh2    = (const float*)d_in[13];
    const float* bh2    = (const float*)d_in[14];
    const float* Wx1    = (const float*)d_in[15];
    const float* bx1    = (const float*)d_in[16];
    const float* Wx2    = (const float*)d_in[17];
    const float* Wm     = (const float*)d_in[18];
    const float* bm     = (const float*)d_in[19];

    const int* ei = edges;
    const int* ej = edges + N_EDGES;

    float* out  = (float*)d_out;
    float* hout = out;
    float* xout = out + (size_t)N_NODES * NH;
    float* mout = xout + (size_t)N_NODES * 4;

    int smem3a = (NFH * NH + 64 * SF3 + NH) * 4;
    cudaFuncSetAttribute(k3a_node1, cudaFuncAttributeMaxDynamicSharedMemorySize, smem3a);

    const int EB = N_EDGES / 64;   // 25000
    const int NB = (N_NODES + 63) / 64;

    k0_zero<<<2048, 256>>>();
    k1a<<<EB, 128>>>(h, ei, We1);
    k1b<<<EB, 128>>>(h, x, ei, ej, We1);
    kbn_finalize<<<1, 128>>>(bn_e_g, bn_e_b, 1.f / (float)N_EDGES, 0);
    k2a<<<EB, 128>>>(ei, We2, be2, Wm, bm, mout);
    k2b<<<EB, 128>>>(x, ei, ej, Wx1, bx1, Wx2, mout);
    k3a_node1<<<NB, 128, smem3a>>>(h, nattr, Wh1, bh1);
    kbn_finalize<<<1, 128>>>(bn_h_g, bn_h_b, 1.f / (float)N_NODES, 1);
    k3c_node2<<<NB, 128>>>(h, x, Wh2, bh2, hout, xout);
}